// round 2
// baseline (speedup 1.0000x reference)
#include <cuda_runtime.h>

// Problem constants
#define NPTS  (1u << 18)      // 262144 points
#define LV    16u             // levels
#define TMASK 0x3FFFFFu       // T = 2^22, power of two -> mask
#define PI2C  2654435761u

// NL[l] = floor(16 * 1.26^l) computed in fp32 like the reference; margins to the
// floor boundary are >= 2e-4 relative, far above fp32 pow error.
__device__ __constant__ float c_NL[16] = {
    16.f, 20.f, 25.f, 32.f, 40.f, 50.f, 64.f, 80.f,
    101.f, 128.f, 161.f, 203.f, 256.f, 322.f, 406.f, 512.f
};

// Bicubic Hermite evaluation for one feature given the 4x4 tap values f[i*4+j]
// (i = x offset, j = y offset), replicating the reference's finite-difference
// construction of the Hermite matrix.
__device__ __forceinline__ float eval_bicubic(const float* f,
                                              float wx0, float wx1, float wx2, float wx3,
                                              float wy0, float wy1, float wy2, float wy3) {
    // fy[i][j'] = 0.5*(f[i][j'+2] - f[i][j']),  i in 0..3, j' in 0..1
    float fy[8];
#pragma unroll
    for (int i = 0; i < 4; ++i) {
#pragma unroll
        for (int j = 0; j < 2; ++j) {
            fy[i * 2 + j] = 0.5f * (f[i * 4 + j + 2] - f[i * 4 + j]);
        }
    }
    // fx[i'][j] = 0.5*(f[i'+2][j] - f[i'][j]),  i' in 0..1, j in 0..3
    float fx[8];
#pragma unroll
    for (int i = 0; i < 2; ++i) {
#pragma unroll
        for (int j = 0; j < 4; ++j) {
            fx[i * 4 + j] = 0.5f * (f[(i + 2) * 4 + j] - f[i * 4 + j]);
        }
    }
    // fxy[i'][j'] = 0.25*((fy[i'+2][j'] - fy[i'][j']) + (fx[i'][j'+2] - fx[i'][j']))
    float fxy[4];
#pragma unroll
    for (int i = 0; i < 2; ++i) {
#pragma unroll
        for (int j = 0; j < 2; ++j) {
            fxy[i * 2 + j] = 0.25f * ((fy[(i + 2) * 2 + j] - fy[i * 2 + j]) +
                                      (fx[i * 4 + j + 2] - fx[i * 4 + j]));
        }
    }
    // Hermite matrix Fm (4x4), rows c, cols g
    float Fm[16] = {
        f[1 * 4 + 1], f[1 * 4 + 2], fy[1 * 2 + 0], fy[1 * 2 + 1],
        f[2 * 4 + 1], f[2 * 4 + 2], fy[2 * 2 + 0], fy[2 * 2 + 1],
        fx[0 * 4 + 1], fx[0 * 4 + 2], fxy[0],       fxy[1],
        fx[1 * 4 + 1], fx[1 * 4 + 2], fxy[2],       fxy[3]
    };
    // out = sum_c wx[c] * (sum_g Fm[c][g] * wy[g])
    float v0 = Fm[0] * wy0 + Fm[1] * wy1 + Fm[2] * wy2 + Fm[3] * wy3;
    float v1 = Fm[4] * wy0 + Fm[5] * wy1 + Fm[6] * wy2 + Fm[7] * wy3;
    float v2 = Fm[8] * wy0 + Fm[9] * wy1 + Fm[10] * wy2 + Fm[11] * wy3;
    float v3 = Fm[12] * wy0 + Fm[13] * wy1 + Fm[14] * wy2 + Fm[15] * wy3;
    return wx0 * v0 + wx1 * v1 + wx2 * v2 + wx3 * v3;
}

// One thread per (point, level). lane = level (16 levels -> 2 points per warp)
// so the float2 output store is fully coalesced (256B per warp).
__global__ void __launch_bounds__(256)
enc_cubic_kernel(const float* __restrict__ x,
                 const float* __restrict__ tab,
                 float* __restrict__ out) {
    unsigned t = blockIdx.x * 256u + threadIdx.x;
    unsigned n = t >> 4;
    unsigned l = t & 15u;

    float2 p = reinterpret_cast<const float2*>(x)[n];
    float NL = c_NL[l];
    float xs = p.x * NL;
    float ys = p.y * NL;
    int ixi = (int)xs;      // x >= 0, trunc == floor
    int iyi = (int)ys;
    float lx = xs - (float)ixi;
    float ly = ys - (float)iyi;

    // Hash all 16 taps
    unsigned baseoff[16];
#pragma unroll
    for (int j = 0; j < 4; ++j) {
        unsigned hy = (unsigned)(iyi + j) * PI2C;
#pragma unroll
        for (int i = 0; i < 4; ++i) {
            unsigned idx = (((unsigned)(ixi + i)) ^ hy) & TMASK;
            baseoff[i * 4 + j] = idx * 32u + l;   // row stride = FPL*L = 32 floats
        }
    }

    // Issue all 32 gathers up front for maximum MLP
    float f0[16], f1[16];
#pragma unroll
    for (int k = 0; k < 16; ++k) f0[k] = __ldg(tab + baseoff[k]);
#pragma unroll
    for (int k = 0; k < 16; ++k) f1[k] = __ldg(tab + baseoff[k] + 16u);

    // Hermite basis weights: wx = [1,t,t^2,t^3] @ B
    float x2 = lx * lx, x3 = x2 * lx;
    float wx0 = 1.f - 3.f * x2 + 2.f * x3;
    float wx1 = 3.f * x2 - 2.f * x3;
    float wx2 = lx - 2.f * x2 + x3;
    float wx3 = x3 - x2;
    float y2 = ly * ly, y3 = y2 * ly;
    float wy0 = 1.f - 3.f * y2 + 2.f * y3;
    float wy1 = 3.f * y2 - 2.f * y3;
    float wy2 = ly - 2.f * y2 + y3;
    float wy3 = y3 - y2;

    float o0 = eval_bicubic(f0, wx0, wx1, wx2, wx3, wy0, wy1, wy2, wy3);
    float o1 = eval_bicubic(f1, wx0, wx1, wx2, wx3, wy0, wy1, wy2, wy3);

    // out[n, l*2 + {0,1}] -> float2 store, coalesced across the warp
    reinterpret_cast<float2*>(out)[n * 16u + l] = make_float2(o0, o1);
}

extern "C" void kernel_launch(void* const* d_in, const int* in_sizes, int n_in,
                              void* d_out, int out_size) {
    const float* x   = (const float*)d_in[0];   // (262144, 2) float32
    const float* tab = (const float*)d_in[1];   // (2^22, 2, 16) float32
    float* out = (float*)d_out;                 // (262144, 32) float32

    unsigned total = NPTS * LV;                 // 4,194,304 threads
    enc_cubic_kernel<<<total / 256, 256>>>(x, tab, out);
}

// round 5
// speedup vs baseline: 1.5431x; 1.5431x over previous
#include <cuda_runtime.h>

// Problem constants
#define NPTS  (1u << 18)      // 262144 points
#define LV    16u             // levels
#define TSZ   (1u << 22)      // hash table rows
#define TMASK 0x3FFFFFu
#define PI2C  2654435761u

// Transposed table scratch: (T, L) of float2 (feature pairs). 512 MB static.
__device__ float2 g_scr[TSZ * LV];

// NL[l] = floor(16 * 1.26^l); fp32-pow values are safely away from integer
// boundaries, so the hardcoded floors match the reference exactly.
__device__ __constant__ float c_NL[16] = {
    16.f, 20.f, 25.f, 32.f, 40.f, 50.f, 64.f, 80.f,
    101.f, 128.f, 161.f, 203.f, 256.f, 322.f, 406.f, 512.f
};

// ---------------------------------------------------------------------------
// Pre-pass: (T, 2, 16) float -> (T, 16) float2. One thread per output float2.
// Reads are warp-coalesced within each 128B row; writes are fully coalesced.
// ---------------------------------------------------------------------------
__global__ void __launch_bounds__(256)
transpose_kernel(const float* __restrict__ tab) {
    unsigned t = blockIdx.x * 256u + threadIdx.x;   // [0, T*16)
    unsigned row = t >> 4;
    unsigned l = t & 15u;
    const float* r = tab + row * 32u;
    g_scr[row * 16u + l] = make_float2(__ldg(r + l), __ldg(r + l + 16u));
}

// ---------------------------------------------------------------------------
// Bicubic Hermite evaluation for both features at once (float2 lanes),
// replicating the reference's finite-difference Hermite construction.
// f[i*4+j]: i = x offset, j = y offset.
// ---------------------------------------------------------------------------
__device__ __forceinline__ float2 eval_bicubic2(const float2* f,
                                                float wx0, float wx1, float wx2, float wx3,
                                                float wy0, float wy1, float wy2, float wy3) {
    float2 fy[8];
#pragma unroll
    for (int i = 0; i < 4; ++i)
#pragma unroll
        for (int j = 0; j < 2; ++j) {
            fy[i * 2 + j].x = 0.5f * (f[i * 4 + j + 2].x - f[i * 4 + j].x);
            fy[i * 2 + j].y = 0.5f * (f[i * 4 + j + 2].y - f[i * 4 + j].y);
        }
    float2 fx[8];
#pragma unroll
    for (int i = 0; i < 2; ++i)
#pragma unroll
        for (int j = 0; j < 4; ++j) {
            fx[i * 4 + j].x = 0.5f * (f[(i + 2) * 4 + j].x - f[i * 4 + j].x);
            fx[i * 4 + j].y = 0.5f * (f[(i + 2) * 4 + j].y - f[i * 4 + j].y);
        }
    float2 fxy[4];
#pragma unroll
    for (int i = 0; i < 2; ++i)
#pragma unroll
        for (int j = 0; j < 2; ++j) {
            fxy[i * 2 + j].x = 0.25f * ((fy[(i + 2) * 2 + j].x - fy[i * 2 + j].x) +
                                        (fx[i * 4 + j + 2].x - fx[i * 4 + j].x));
            fxy[i * 2 + j].y = 0.25f * ((fy[(i + 2) * 2 + j].y - fy[i * 2 + j].y) +
                                        (fx[i * 4 + j + 2].y - fx[i * 4 + j].y));
        }
    // Hermite matrix rows (c) x cols (g), per feature
    float2 Fm[16] = {
        f[5], f[6], fy[2], fy[3],
        f[9], f[10], fy[4], fy[5],
        fx[1], fx[2], fxy[0], fxy[1],
        fx[5], fx[6], fxy[2], fxy[3]
    };
    float2 out;
    {
        float v0 = Fm[0].x * wy0 + Fm[1].x * wy1 + Fm[2].x * wy2 + Fm[3].x * wy3;
        float v1 = Fm[4].x * wy0 + Fm[5].x * wy1 + Fm[6].x * wy2 + Fm[7].x * wy3;
        float v2 = Fm[8].x * wy0 + Fm[9].x * wy1 + Fm[10].x * wy2 + Fm[11].x * wy3;
        float v3 = Fm[12].x * wy0 + Fm[13].x * wy1 + Fm[14].x * wy2 + Fm[15].x * wy3;
        out.x = wx0 * v0 + wx1 * v1 + wx2 * v2 + wx3 * v3;
    }
    {
        float v0 = Fm[0].y * wy0 + Fm[1].y * wy1 + Fm[2].y * wy2 + Fm[3].y * wy3;
        float v1 = Fm[4].y * wy0 + Fm[5].y * wy1 + Fm[6].y * wy2 + Fm[7].y * wy3;
        float v2 = Fm[8].y * wy0 + Fm[9].y * wy1 + Fm[10].y * wy2 + Fm[11].y * wy3;
        float v3 = Fm[12].y * wy0 + Fm[13].y * wy1 + Fm[14].y * wy2 + Fm[15].y * wy3;
        out.y = wx0 * v0 + wx1 * v1 + wx2 * v2 + wx3 * v3;
    }
    return out;
}

// ---------------------------------------------------------------------------
// Main kernel: one thread per (point, level); lane = level so output float2
// stores are fully coalesced (256B per warp). 16 LDG.64 gathers per thread,
// all issued before any dependent use for maximum MLP.
// ---------------------------------------------------------------------------
__global__ void __launch_bounds__(256)
enc_cubic_kernel(const float* __restrict__ x,
                 float* __restrict__ out) {
    unsigned t = blockIdx.x * 256u + threadIdx.x;
    unsigned n = t >> 4;
    unsigned l = t & 15u;

    float2 p = reinterpret_cast<const float2*>(x)[n];
    float NL = c_NL[l];
    float xs = p.x * NL;
    float ys = p.y * NL;
    int ixi = (int)xs;
    int iyi = (int)ys;
    float lx = xs - (float)ixi;
    float ly = ys - (float)iyi;

    // Hash 16 taps -> scratch offsets
    unsigned off[16];
#pragma unroll
    for (int j = 0; j < 4; ++j) {
        unsigned hy = (unsigned)(iyi + j) * PI2C;
#pragma unroll
        for (int i = 0; i < 4; ++i) {
            unsigned idx = (((unsigned)(ixi + i)) ^ hy) & TMASK;
            off[i * 4 + j] = idx * 16u + l;
        }
    }

    // 16 independent float2 gathers
    float2 f[16];
#pragma unroll
    for (int k = 0; k < 16; ++k) f[k] = __ldg(&g_scr[off[k]]);

    // Hermite basis weights
    float x2 = lx * lx, x3 = x2 * lx;
    float wx0 = 1.f - 3.f * x2 + 2.f * x3;
    float wx1 = 3.f * x2 - 2.f * x3;
    float wx2 = lx - 2.f * x2 + x3;
    float wx3 = x3 - x2;
    float y2 = ly * ly, y3 = y2 * ly;
    float wy0 = 1.f - 3.f * y2 + 2.f * y3;
    float wy1 = 3.f * y2 - 2.f * y3;
    float wy2 = ly - 2.f * y2 + y3;
    float wy3 = y3 - y2;

    float2 o = eval_bicubic2(f, wx0, wx1, wx2, wx3, wy0, wy1, wy2, wy3);

    reinterpret_cast<float2*>(out)[n * 16u + l] = o;
}

extern "C" void kernel_launch(void* const* d_in, const int* in_sizes, int n_in,
                              void* d_out, int out_size) {
    const float* x   = (const float*)d_in[0];   // (262144, 2) float32
    const float* tab = (const float*)d_in[1];   // (2^22, 2, 16) float32
    float* out = (float*)d_out;                 // (262144, 32) float32

    // Pre-pass: transpose table into (T, L, float2) scratch
    transpose_kernel<<<(TSZ * LV) / 256, 256>>>(tab);

    // Main gather + bicubic kernel
    enc_cubic_kernel<<<(NPTS * LV) / 256, 256>>>(x, out);
}

// round 6
// speedup vs baseline: 4.8190x; 3.1229x over previous
#include <cuda_runtime.h>

#define NPTS  (1u << 18)
#define TMASK 0x3FFFFFu
#define PI2C  2654435761u

// NL[l] = floor(16 * 1.26^l) per reference fp32 math (verified, rel_err 1.2e-7)
__device__ __constant__ float c_NL[16] = {
    16.f, 20.f, 25.f, 32.f, 40.f, 50.f, 64.f, 80.f,
    101.f, 128.f, 161.f, 203.f, 256.f, 322.f, 406.f, 512.f
};
// Dense grid width per level: W = NL + 3 (gx in [0, NL+2])
__device__ __constant__ int c_W[16] = {
    19, 23, 28, 35, 43, 53, 67, 83, 104, 131, 164, 206, 259, 325, 409, 515
};
// Prefix sums of W^2
__device__ __constant__ int c_base[16] = {
    0, 361, 890, 1674, 2899, 4748, 7557, 12046,
    18935, 29751, 46912, 73808, 116244, 183325, 288950, 456231
};
#define DENSE_TOTAL 721456

// Dense per-level grids of feature pairs: 5.8 MB (L2-resident)
__device__ float2 g_dense[DENSE_TOTAL];

// ---------------------------------------------------------------------------
// Pre-pass: evaluate the hash once per reachable grid cell, gather the two
// features from the original (T, 2, 16) table, write dense[l][cy][cx].
// 721K cells x 2 gathers -- trivial vs the 67M point-side gathers.
// ---------------------------------------------------------------------------
__global__ void __launch_bounds__(256)
densify_kernel(const float* __restrict__ tab) {
    int l = blockIdx.y;
    int W = c_W[l];
    int tot = W * W;
    int idx = blockIdx.x * 256 + threadIdx.x;
    if (idx >= tot) return;
    int cy = idx / W;
    int cx = idx - cy * W;
    unsigned h = (((unsigned)cx) ^ ((unsigned)cy * PI2C)) & TMASK;
    const float* r = tab + h * 32u;
    g_dense[c_base[l] + idx] = make_float2(__ldg(r + l), __ldg(r + l + 16));
}

// Catmull-Rom-style separable cubic weight k in {0,1,2,3} at parameter t.
// Derived from the reference's Hermite + finite-difference construction:
//   out = sum_ij a_i(lx) * b_j(ly) * f[i][j]
__device__ __forceinline__ float cubw(float t, int k) {
    float t2 = t * t, t3 = t2 * t;
    float h00 = 1.f - 3.f * t2 + 2.f * t3;
    float h01 = 3.f * t2 - 2.f * t3;
    float h10 = t3 - 2.f * t2 + t;
    float h11 = t3 - t2;
    float a0 = -0.5f * h10;
    float a1 = h00 - 0.5f * h11;
    float a2 = h01 + 0.5f * h10;
    float a3 = 0.5f * h11;
    return k == 0 ? a0 : (k == 1 ? a1 : (k == 2 ? a2 : a3));
}

// ---------------------------------------------------------------------------
// Main kernel: one block per point; 256 threads = 16 levels x 16 taps.
// Each lane does ONE float2 gather from the dense grid. Taps (i=0..3, j fixed)
// are 4 consecutive float2 -> coalesce into ~1 line per row, ~10 lines per
// warp-LDG (vs ~32 before). Butterfly reduce over the 16-lane tap group.
// ---------------------------------------------------------------------------
__global__ void __launch_bounds__(256)
enc_cubic_kernel(const float* __restrict__ x,
                 float* __restrict__ out) {
    unsigned n = blockIdx.x;
    int tid = threadIdx.x;
    int l = tid >> 4;          // level
    int lane16 = tid & 15;     // tap id within group
    int i = lane16 & 3;        // x offset
    int j = lane16 >> 2;       // y offset

    float2 p = reinterpret_cast<const float2*>(x)[n];  // broadcast load
    float NL = c_NL[l];
    float xs = p.x * NL;
    float ys = p.y * NL;
    int ixi = (int)xs;
    int iyi = (int)ys;
    float lx = xs - (float)ixi;
    float ly = ys - (float)iyi;

    int W = c_W[l];
    float2 f = __ldg(&g_dense[c_base[l] + (iyi + j) * W + (ixi + i)]);

    float w = cubw(lx, i) * cubw(ly, j);
    float v0 = w * f.x;
    float v1 = w * f.y;

    // Reduce over the 16-lane tap group (xor offsets < 16 stay in-group)
#pragma unroll
    for (int off = 8; off; off >>= 1) {
        v0 += __shfl_xor_sync(0xffffffffu, v0, off);
        v1 += __shfl_xor_sync(0xffffffffu, v1, off);
    }

    if (lane16 == 0)
        reinterpret_cast<float2*>(out)[n * 16u + l] = make_float2(v0, v1);
}

extern "C" void kernel_launch(void* const* d_in, const int* in_sizes, int n_in,
                              void* d_out, int out_size) {
    const float* x   = (const float*)d_in[0];   // (262144, 2) float32
    const float* tab = (const float*)d_in[1];   // (2^22, 2, 16) float32
    float* out = (float*)d_out;                 // (262144, 32) float32

    // Pre-pass: build dense per-level grids (hash evaluated per CELL, not per point)
    dim3 dgrid((265225 + 255) / 256, 16);
    densify_kernel<<<dgrid, 256>>>(tab);

    // Main: one block per point
    enc_cubic_kernel<<<NPTS, 256>>>(x, out);
}

// round 7
// speedup vs baseline: 5.0471x; 1.0473x over previous
#include <cuda_runtime.h>

#define NPTS  (1u << 18)
#define TMASK 0x3FFFFFu
#define PI2C  2654435761u
#define PTS_PER_BLK 16

// NL[l] = floor(16 * 1.26^l) per reference fp32 math (verified, rel_err ~1.2e-7)
__device__ __constant__ float c_NL[16] = {
    16.f, 20.f, 25.f, 32.f, 40.f, 50.f, 64.f, 80.f,
    101.f, 128.f, 161.f, 203.f, 256.f, 322.f, 406.f, 512.f
};
// Dense grid width per level: W = NL + 3
__device__ __constant__ int c_W[16] = {
    19, 23, 28, 35, 43, 53, 67, 83, 104, 131, 164, 206, 259, 325, 409, 515
};
// Prefix sums of W^2
__device__ __constant__ int c_base[16] = {
    0, 361, 890, 1674, 2899, 4748, 7557, 12046,
    18935, 29751, 46912, 73808, 116244, 183325, 288950, 456231
};
#define DENSE_TOTAL 721456

// Dense per-level grids of feature pairs: 5.8 MB (L2-resident)
__device__ float2 g_dense[DENSE_TOTAL];

// ---------------------------------------------------------------------------
// Pre-pass: hash evaluated once per reachable grid cell (721K cells).
// ---------------------------------------------------------------------------
__global__ void __launch_bounds__(256)
densify_kernel(const float* __restrict__ tab) {
    int l = blockIdx.y;
    int W = c_W[l];
    int tot = W * W;
    int idx = blockIdx.x * 256 + threadIdx.x;
    if (idx >= tot) return;
    int cy = idx / W;
    int cx = idx - cy * W;
    unsigned h = (((unsigned)cx) ^ ((unsigned)cy * PI2C)) & TMASK;
    const float* r = tab + h * 32u;
    g_dense[c_base[l] + idx] = make_float2(__ldg(r + l), __ldg(r + l + 16));
}

// Catmull-Rom-style weight polynomial coefficients for tap index k:
//   w_k(t) = A t^3 + B t^2 + C t + D
// Derived from the reference Hermite + finite-difference construction.
__device__ __forceinline__ void cub_coef(int k, float& A, float& B, float& C, float& D) {
    if (k == 0)      { A = -0.5f; B =  1.0f; C = -0.5f; D = 0.f; }
    else if (k == 1) { A =  1.5f; B = -2.5f; C =  0.0f; D = 1.f; }
    else if (k == 2) { A = -1.5f; B =  2.0f; C =  0.5f; D = 0.f; }
    else             { A =  0.5f; B = -0.5f; C =  0.0f; D = 0.f; }
}

// ---------------------------------------------------------------------------
// Main kernel: 256 threads = 16 levels x 16 taps; each block loops over
// PTS_PER_BLK points so all lane-constant state (level constants + this
// lane's cubic coefficients) is computed once and amortized.
// ---------------------------------------------------------------------------
__global__ void __launch_bounds__(256)
enc_cubic_kernel(const float* __restrict__ x,
                 float* __restrict__ out) {
    int tid = threadIdx.x;
    int l = tid >> 4;          // level
    int lane16 = tid & 15;     // tap id within group
    int i = lane16 & 3;        // x tap offset
    int j = lane16 >> 2;       // y tap offset

    // Lane-constant state (amortized over PTS_PER_BLK points)
    float NL = c_NL[l];
    int W = c_W[l];
    const float2* grid = g_dense + c_base[l] + j * W + i;  // fold tap offsets in
    float Ax, Bx, Cx, Dx, Ay, By, Cy, Dy;
    cub_coef(i, Ax, Bx, Cx, Dx);
    cub_coef(j, Ay, By, Cy, Dy);

    unsigned n0 = blockIdx.x * PTS_PER_BLK;
    const float2* xp = reinterpret_cast<const float2*>(x);
    float2* outp = reinterpret_cast<float2*>(out);

#pragma unroll
    for (int it = 0; it < PTS_PER_BLK; ++it) {
        unsigned n = n0 + it;
        float2 p = __ldg(&xp[n]);          // uniform across block -> 1 wavefront
        float xs = p.x * NL;
        float ys = p.y * NL;
        int ixi = (int)xs;
        int iyi = (int)ys;
        float lx = xs - (float)ixi;
        float ly = ys - (float)iyi;

        float wx = ((Ax * lx + Bx) * lx + Cx) * lx + Dx;
        float wy = ((Ay * ly + By) * ly + Cy) * ly + Dy;
        float w = wx * wy;

        float2 f = __ldg(grid + iyi * W + ixi);
        float v0 = w * f.x;
        float v1 = w * f.y;

        // Butterfly reduce over the 16-lane tap group
#pragma unroll
        for (int off = 8; off; off >>= 1) {
            v0 += __shfl_xor_sync(0xffffffffu, v0, off);
            v1 += __shfl_xor_sync(0xffffffffu, v1, off);
        }

        if (lane16 == 0)
            outp[n * 16u + l] = make_float2(v0, v1);
    }
}

extern "C" void kernel_launch(void* const* d_in, const int* in_sizes, int n_in,
                              void* d_out, int out_size) {
    const float* x   = (const float*)d_in[0];   // (262144, 2) float32
    const float* tab = (const float*)d_in[1];   // (2^22, 2, 16) float32
    float* out = (float*)d_out;                 // (262144, 32) float32

    dim3 dgrid((265225 + 255) / 256, 16);
    densify_kernel<<<dgrid, 256>>>(tab);

    enc_cubic_kernel<<<NPTS / PTS_PER_BLK, 256>>>(x, out);
}

// round 8
// speedup vs baseline: 9.4506x; 1.8725x over previous
#include <cuda_runtime.h>

#define NPTS  (1u << 18)
#define TMASK 0x3FFFFFu
#define PI2C  2654435761u
#define PTS_PER_BLK 16

// NL[l] = floor(16 * 1.26^l) per reference fp32 math (verified, rel_err ~1.4e-7)
__device__ __constant__ float c_NL[16] = {
    16.f, 20.f, 25.f, 32.f, 40.f, 50.f, 64.f, 80.f,
    101.f, 128.f, 161.f, 203.f, 256.f, 322.f, 406.f, 512.f
};
// Dense grid width per level: W = NL + 3
__device__ __constant__ int c_W[16] = {
    19, 23, 28, 35, 43, 53, 67, 83, 104, 131, 164, 206, 259, 325, 409, 515
};
// Tile-grid width per level: Wt = ceil(W / 4)
__device__ __constant__ int c_Wt[16] = {
    5, 6, 7, 9, 11, 14, 17, 21, 26, 33, 41, 52, 65, 82, 103, 129
};
// Prefix sums of Wt^2 * 16 cells (tiled layout, 128B line-aligned tiles)
__device__ __constant__ int c_tbase[16] = {
    0, 400, 976, 1760, 3056, 4992, 8128, 12752,
    19808, 30624, 48048, 74944, 118208, 185808, 293392, 463136
};
#define DENSE_TOTAL 729392
#define MAX_LVL_CELLS 266256

// Dense per-level grids in 4x4-cell tiles (one tile = 16 float2 = 128B = 1 line)
__device__ __align__(128) float2 g_dense[DENSE_TOTAL];

// ---------------------------------------------------------------------------
// Pre-pass: hash evaluated once per reachable grid cell; write tiled layout.
// ---------------------------------------------------------------------------
__global__ void __launch_bounds__(256)
densify_kernel(const float* __restrict__ tab) {
    int l = blockIdx.y;
    int W = c_W[l];
    int Wt = c_Wt[l];
    int tot = Wt * Wt * 16;
    int idx = blockIdx.x * 256 + threadIdx.x;
    if (idx >= tot) return;
    int t = idx >> 4;                 // tile id
    int off = idx & 15;               // cell within tile
    int ty = t / Wt;
    int tx = t - ty * Wt;
    int cx = tx * 4 + (off & 3);
    int cy = ty * 4 + (off >> 2);
    if (cx >= W || cy >= W) return;   // padding cells never read
    unsigned h = (((unsigned)cx) ^ ((unsigned)cy * PI2C)) & TMASK;
    const float* r = tab + h * 32u;
    g_dense[c_tbase[l] + idx] = make_float2(__ldg(r + l), __ldg(r + l + 16));
}

// Catmull-Rom-style weight polynomial coefficients for tap index k:
//   w_k(t) = A t^3 + B t^2 + C t + D   (from the reference Hermite+FD algebra)
__device__ __forceinline__ void cub_coef(int k, float& A, float& B, float& C, float& D) {
    if (k == 0)      { A = -0.5f; B =  1.0f; C = -0.5f; D = 0.f; }
    else if (k == 1) { A =  1.5f; B = -2.5f; C =  0.0f; D = 1.f; }
    else if (k == 2) { A = -1.5f; B =  2.0f; C =  0.5f; D = 0.f; }
    else             { A =  0.5f; B = -0.5f; C =  0.0f; D = 0.f; }
}

// ---------------------------------------------------------------------------
// Main kernel: 256 threads = 16 levels x 16 taps, looping over 16 points.
// Tiled gather (<= ~3 lines per 4x4 window) + 5-shuffle feature-split reduce.
// ---------------------------------------------------------------------------
__global__ void __launch_bounds__(256)
enc_cubic_kernel(const float* __restrict__ x,
                 float* __restrict__ out) {
    int tid = threadIdx.x;
    int l = tid >> 4;          // level
    int lane16 = tid & 15;     // tap id within group
    int i = lane16 & 3;        // x tap offset
    int j = lane16 >> 2;       // y tap offset

    // Lane-constant state
    float NL = c_NL[l];
    int Wt = c_Wt[l];
    const float2* grid = g_dense + c_tbase[l];
    float Ax, Bx, Cx, Dx, Ay, By, Cy, Dy;
    cub_coef(i, Ax, Bx, Cx, Dx);
    cub_coef(j, Ay, By, Cy, Dy);

    unsigned n0 = blockIdx.x * PTS_PER_BLK;
    const float2* xp = reinterpret_cast<const float2*>(x);
    // Output slot for this lane (only lanes 0 and 8 of each group store):
    // lane 0 -> feature 0, lane 8 -> feature 1.
    int ocol = l * 2 + (lane16 >> 3);
    bool storer = (lane16 & 7) == 0;

#pragma unroll
    for (int it = 0; it < PTS_PER_BLK; ++it) {
        unsigned n = n0 + it;
        float2 p = __ldg(&xp[n]);          // uniform across block
        float xs = p.x * NL;
        float ys = p.y * NL;
        int ixi = (int)xs;
        int iyi = (int)ys;
        float lx = xs - (float)ixi;
        float ly = ys - (float)iyi;

        // Tiled address for this lane's tap
        int gx = ixi + i;
        int gy = iyi + j;
        int tx = gx >> 2, ox = gx & 3;
        int ty = gy >> 2, oy = gy & 3;
        float2 f = __ldg(&grid[((ty * Wt + tx) << 4) + (oy << 2) + ox]);

        float wx = ((Ax * lx + Bx) * lx + Cx) * lx + Dx;
        float wy = ((Ay * ly + By) * ly + Cy) * ly + Dy;
        float w = wx * wy;
        float v0 = w * f.x;
        float v1 = w * f.y;

        // Feature-split reduction: 5 shuffles instead of 8.
        // Step 1 (xor 8): low half accumulates feature0, high half feature1.
        float pv0 = __shfl_xor_sync(0xffffffffu, v0, 8);
        float pv1 = __shfl_xor_sync(0xffffffffu, v1, 8);
        float s = (lane16 & 8) ? (v1 + pv1) : (v0 + pv0);
        s += __shfl_xor_sync(0xffffffffu, s, 4);
        s += __shfl_xor_sync(0xffffffffu, s, 2);
        s += __shfl_xor_sync(0xffffffffu, s, 1);

        if (storer)
            out[n * 32u + ocol] = s;
    }
}

extern "C" void kernel_launch(void* const* d_in, const int* in_sizes, int n_in,
                              void* d_out, int out_size) {
    const float* x   = (const float*)d_in[0];   // (262144, 2) float32
    const float* tab = (const float*)d_in[1];   // (2^22, 2, 16) float32
    float* out = (float*)d_out;                 // (262144, 32) float32

    dim3 dgrid((MAX_LVL_CELLS + 255) / 256, 16);
    densify_kernel<<<dgrid, 256>>>(tab);

    enc_cubic_kernel<<<NPTS / PTS_PER_BLK, 256>>>(x, out);
}